// round 2
// baseline (speedup 1.0000x reference)
#include <cuda_runtime.h>

#define NF 8
#define NK 16
#define BB 32
#define YY 32
#define XX 32
#define PP 16
#define TT 8
// row length (per b,f,y): X*P*T = 4096 floats = 16KB

__device__ float g_ky[NF*NK*YY];
__device__ float g_kx[NF*NK*XX];
__device__ float g_kp[NF*NK*PP];
__device__ float g_kt[NF*NK*TT];
__device__ float g_qmean[YY*XX*PP*TT];
__device__ float g_integral[NF*NK];

// ---- packed f32x2 helpers (Blackwell FFMA2) ----
__device__ __forceinline__ float2 ffma2(float2 a, float2 b, float2 c) {
    float2 d;
    asm("{\n\t"
        ".reg .b64 ra, rb, rc, rd;\n\t"
        "mov.b64 ra, {%2, %3};\n\t"
        "mov.b64 rb, {%4, %5};\n\t"
        "mov.b64 rc, {%6, %7};\n\t"
        "fma.rn.f32x2 rd, ra, rb, rc;\n\t"
        "mov.b64 {%0, %1}, rd;\n\t"
        "}"
        : "=f"(d.x), "=f"(d.y)
        : "f"(a.x), "f"(a.y), "f"(b.x), "f"(b.y), "f"(c.x), "f"(c.y));
    return d;
}
__device__ __forceinline__ float2 fmul2(float2 a, float2 b) {
    float2 d;
    asm("{\n\t"
        ".reg .b64 ra, rb, rd;\n\t"
        "mov.b64 ra, {%2, %3};\n\t"
        "mov.b64 rb, {%4, %5};\n\t"
        "mul.rn.f32x2 rd, ra, rb;\n\t"
        "mov.b64 {%0, %1}, rd;\n\t"
        "}"
        : "=f"(d.x), "=f"(d.y)
        : "f"(a.x), "f"(a.y), "f"(b.x), "f"(b.y));
    return d;
}

// ---- Kernel A: build 1-D separable tables, zero accumulators + output ----
__global__ void setup_kernel(const float* __restrict__ mean_lat, const float* __restrict__ logstd_lat,
                             const float* __restrict__ mean_lon, const float* __restrict__ logstd_lon,
                             const float* __restrict__ mean_lev, const float* __restrict__ logstd_lev,
                             const float* __restrict__ logtau,   float* __restrict__ out) {
    int tid = threadIdx.x;               // 128 threads = (f,k)
    // lat -> ky (len 32), coord = linspace(-1,1,32)
    {
        float m = mean_lat[tid], inv_s = 1.0f / expf(logstd_lat[tid]);
        #pragma unroll
        for (int i = 0; i < YY; ++i) {
            float c = -1.0f + 2.0f * (float)i / (float)(YY - 1);
            float z = (c - m) * inv_s;
            g_ky[tid * YY + i] = expf(-0.5f * z * z);
        }
    }
    // lon -> kx (len 32)
    {
        float m = mean_lon[tid], inv_s = 1.0f / expf(logstd_lon[tid]);
        #pragma unroll
        for (int i = 0; i < XX; ++i) {
            float c = -1.0f + 2.0f * (float)i / (float)(XX - 1);
            float z = (c - m) * inv_s;
            g_kx[tid * XX + i] = expf(-0.5f * z * z);
        }
    }
    // lev -> kp (len 16)
    {
        float m = mean_lev[tid], inv_s = 1.0f / expf(logstd_lev[tid]);
        #pragma unroll
        for (int i = 0; i < PP; ++i) {
            float c = -1.0f + 2.0f * (float)i / (float)(PP - 1);
            float z = (c - m) * inv_s;
            g_kp[tid * PP + i] = expf(-0.5f * z * z);
        }
    }
    // time -> kt (len 8), exp(-t/tau), tau = exp(logtau)+1e-4
    {
        float inv_tau = 1.0f / (expf(logtau[tid]) + 1e-4f);
        #pragma unroll
        for (int t = 0; t < TT; ++t)
            g_kt[tid * TT + t] = expf(-(float)t * inv_tau);
    }
    g_integral[tid] = 0.0f;
    #pragma unroll
    for (int i = 0; i < BB; ++i)
        out[tid * BB + i] = 0.0f;        // zero all 4096 outputs (raw accumulators)
}

// ---- Kernel B: qmean over batch ----
__global__ void qmean_kernel(const float* __restrict__ quad) {
    int i = blockIdx.x * 256 + threadIdx.x;   // 131072 threads
    float s = 0.0f;
    #pragma unroll
    for (int b = 0; b < BB; ++b)
        s += quad[b * (YY*XX*PP*TT) + i];
    g_qmean[i] = s * (1.0f / (float)BB);
}

// ---- Kernel C: integral[f,k] = sum_i kernel * qmean (separable contraction) ----
__global__ void integral_kernel() {
    __shared__ float sq[PP*TT];
    int tid = threadIdx.x;                 // 128 = (f,k)
    int blk = blockIdx.x;                  // 1024 = y*32+x
    sq[tid] = g_qmean[blk * (PP*TT) + tid];
    __syncthreads();
    int y = blk >> 5, x = blk & 31;
    const float* kt = &g_kt[tid * TT];
    const float* kp = &g_kp[tid * PP];
    float s = 0.0f;
    #pragma unroll
    for (int p = 0; p < PP; ++p) {
        float st = 0.0f;
        #pragma unroll
        for (int t = 0; t < TT; ++t)
            st += kt[t] * sq[p * TT + t];
        s += kp[p] * st;
    }
    float partial = s * g_ky[tid * YY + y] * g_kx[tid * XX + x];
    atomicAdd(&g_integral[tid], partial);
}

// ---- Kernel D: main fused features pass ----
// grid = 512 blocks: (b, y-chunk of 2). 256 threads = 8 warps (one per f).
// Lane l owns (p = l>>1, t in [ (l&1)*4, +4 )) -> kp*kt weights are per-lane
// register constants. Field reads fully coalesced. Quad staged in shared once.
__global__ __launch_bounds__(256)
void feat_kernel(const float* __restrict__ field, const float* __restrict__ quad,
                 float* __restrict__ out) {
    __shared__ float4 sq4[1024];              // 16KB quad row (one y)
    __shared__ float2 s_c2[NF * 8 * XX];      // 16KB: ky*kx per (f, k-pair, x)

    const int tid  = threadIdx.x;
    const int f    = tid >> 5;
    const int lane = tid & 31;
    const int b    = blockIdx.x >> 4;         // 32
    const int ych  = blockIdx.x & 15;         // 16 chunks of 2 y
    const int p    = lane >> 1;
    const int t0   = (lane & 1) * 4;

    // per-lane packed weights: w2[m][j] = (kp[2m]*kt[2m], kp[2m+1]*kt[2m+1]) at (p, t0+j)
    float2 w2[8][4];
    #pragma unroll
    for (int m = 0; m < 8; ++m) {
        int k0 = 2 * m, k1 = 2 * m + 1;
        float kp0 = g_kp[(f * NK + k0) * PP + p];
        float kp1 = g_kp[(f * NK + k1) * PP + p];
        #pragma unroll
        for (int j = 0; j < 4; ++j) {
            w2[m][j].x = kp0 * g_kt[(f * NK + k0) * TT + t0 + j];
            w2[m][j].y = kp1 * g_kt[(f * NK + k1) * TT + t0 + j];
        }
    }
    float2 acc[8];
    #pragma unroll
    for (int m = 0; m < 8; ++m) acc[m] = make_float2(0.0f, 0.0f);

    for (int yy = 0; yy < 2; ++yy) {
        int y = ych * 2 + yy;
        __syncthreads();   // previous iteration's reads done before overwrite
        // stage quad row (16KB) cooperatively, coalesced
        const float4* qrow = reinterpret_cast<const float4*>(quad + (size_t)(b * YY + y) * 4096);
        #pragma unroll
        for (int i = 0; i < 4; ++i)
            sq4[tid + 256 * i] = qrow[tid + 256 * i];
        // build ky*kx table for this y: 2048 float2, 8 per thread
        #pragma unroll
        for (int e = 0; e < 8; ++e) {
            int idx = tid * 8 + e;
            int ff = idx >> 8;
            int m  = (idx >> 5) & 7;
            int x  = idx & 31;
            float ky0 = g_ky[(ff * NK + 2 * m) * YY + y];
            float ky1 = g_ky[(ff * NK + 2 * m + 1) * YY + y];
            float kx0 = g_kx[(ff * NK + 2 * m) * XX + x];
            float kx1 = g_kx[(ff * NK + 2 * m + 1) * XX + x];
            s_c2[idx] = make_float2(ky0 * kx0, ky1 * kx1);
        }
        __syncthreads();

        const float4* frow = reinterpret_cast<const float4*>(
            field + (size_t)((b * NF + f) * YY + y) * 4096);
        const float2* cf = &s_c2[f * 8 * XX];

        #pragma unroll 4
        for (int x = 0; x < XX; ++x) {
            float4 fv = frow[x * 32 + lane];   // contiguous 512B per warp-instr
            float4 qv = sq4[x * 32 + lane];    // conflict-free LDS.128
            float g0 = fv.x * qv.x;
            float g1 = fv.y * qv.y;
            float g2 = fv.z * qv.z;
            float g3 = fv.w * qv.w;
            float2 gg0 = make_float2(g0, g0);
            float2 gg1 = make_float2(g1, g1);
            float2 gg2 = make_float2(g2, g2);
            float2 gg3 = make_float2(g3, g3);
            #pragma unroll
            for (int m = 0; m < 8; ++m) {
                float2 s = fmul2(gg0, w2[m][0]);
                s = ffma2(gg1, w2[m][1], s);
                s = ffma2(gg2, w2[m][2], s);
                s = ffma2(gg3, w2[m][3], s);
                acc[m] = ffma2(s, cf[m * XX + x], acc[m]);  // fold ky*kx
            }
        }
    }

    // warp reduction over lanes (= over p,t), then one atomic per (k)
    #pragma unroll
    for (int m = 0; m < 8; ++m) {
        float sx = acc[m].x, sy = acc[m].y;
        #pragma unroll
        for (int off = 16; off > 0; off >>= 1) {
            sx += __shfl_down_sync(0xffffffffu, sx, off);
            sy += __shfl_down_sync(0xffffffffu, sy, off);
        }
        if (lane == 0) {
            atomicAdd(&out[b * (NF * NK) + f * NK + 2 * m],     sx);
            atomicAdd(&out[b * (NF * NK) + f * NK + 2 * m + 1], sy);
        }
    }
}

// ---- Kernel E: normalize by integral ----
__global__ void norm_kernel(float* __restrict__ out) {
    int i = blockIdx.x * 256 + threadIdx.x;   // 4096
    out[i] = out[i] / (g_integral[i & 127] + 1e-4f);
}

extern "C" void kernel_launch(void* const* d_in, const int* in_sizes, int n_in,
                              void* d_out, int out_size) {
    const float* field      = (const float*)d_in[0];
    const float* quad       = (const float*)d_in[1];
    const float* mean_lat   = (const float*)d_in[2];
    const float* logstd_lat = (const float*)d_in[3];
    const float* mean_lon   = (const float*)d_in[4];
    const float* logstd_lon = (const float*)d_in[5];
    const float* mean_lev   = (const float*)d_in[6];
    const float* logstd_lev = (const float*)d_in[7];
    const float* logtau     = (const float*)d_in[8];
    float* out = (float*)d_out;

    setup_kernel<<<1, 128>>>(mean_lat, logstd_lat, mean_lon, logstd_lon,
                             mean_lev, logstd_lev, logtau, out);
    qmean_kernel<<<512, 256>>>(quad);
    integral_kernel<<<1024, 128>>>();
    feat_kernel<<<512, 256>>>(field, quad, out);
    norm_kernel<<<16, 256>>>(out);
}

// round 3
// speedup vs baseline: 1.4128x; 1.4128x over previous
#include <cuda_runtime.h>

#define NF 8
#define NK 16
#define BB 32
#define YY 32
#define XX 32
#define PP 16
#define TT 8

__device__ float g_ky[NF*NK*YY];
__device__ float g_kx[NF*NK*XX];
__device__ float g_kp[NF*NK*PP];
__device__ float g_kt[NF*NK*TT];
__device__ float g_qmean[YY*XX*PP*TT];
__device__ float g_integral[NF*NK];

// ---- packed f32x2 helpers (Blackwell FFMA2) ----
__device__ __forceinline__ float2 ffma2(float2 a, float2 b, float2 c) {
    float2 d;
    asm("{\n\t"
        ".reg .b64 ra, rb, rc, rd;\n\t"
        "mov.b64 ra, {%2, %3};\n\t"
        "mov.b64 rb, {%4, %5};\n\t"
        "mov.b64 rc, {%6, %7};\n\t"
        "fma.rn.f32x2 rd, ra, rb, rc;\n\t"
        "mov.b64 {%0, %1}, rd;\n\t"
        "}"
        : "=f"(d.x), "=f"(d.y)
        : "f"(a.x), "f"(a.y), "f"(b.x), "f"(b.y), "f"(c.x), "f"(c.y));
    return d;
}
__device__ __forceinline__ float2 fmul2(float2 a, float2 b) {
    float2 d;
    asm("{\n\t"
        ".reg .b64 ra, rb, rd;\n\t"
        "mov.b64 ra, {%2, %3};\n\t"
        "mov.b64 rb, {%4, %5};\n\t"
        "mul.rn.f32x2 rd, ra, rb;\n\t"
        "mov.b64 {%0, %1}, rd;\n\t"
        "}"
        : "=f"(d.x), "=f"(d.y)
        : "f"(a.x), "f"(a.y), "f"(b.x), "f"(b.y));
    return d;
}

// ---- Kernel 1: qmean over batch + (block 0) tables + zero out/integral ----
__global__ void prep_kernel(const float* __restrict__ quad,
                            const float* __restrict__ mean_lat, const float* __restrict__ logstd_lat,
                            const float* __restrict__ mean_lon, const float* __restrict__ logstd_lon,
                            const float* __restrict__ mean_lev, const float* __restrict__ logstd_lev,
                            const float* __restrict__ logtau,   float* __restrict__ out) {
    int tid = threadIdx.x;
    int i = blockIdx.x * 256 + tid;        // 512 blocks * 256 = 131072 qmean elems
    float s = 0.0f;
    #pragma unroll
    for (int b = 0; b < BB; ++b)
        s += quad[b * (YY*XX*PP*TT) + i];
    g_qmean[i] = s * (1.0f / (float)BB);

    if (blockIdx.x == 0) {
        if (tid < 128) {
            // lat -> ky (len 32)
            {
                float m = mean_lat[tid], inv_s = 1.0f / expf(logstd_lat[tid]);
                #pragma unroll
                for (int k = 0; k < YY; ++k) {
                    float c = -1.0f + 2.0f * (float)k / (float)(YY - 1);
                    float z = (c - m) * inv_s;
                    g_ky[tid * YY + k] = expf(-0.5f * z * z);
                }
            }
            // lon -> kx (len 32)
            {
                float m = mean_lon[tid], inv_s = 1.0f / expf(logstd_lon[tid]);
                #pragma unroll
                for (int k = 0; k < XX; ++k) {
                    float c = -1.0f + 2.0f * (float)k / (float)(XX - 1);
                    float z = (c - m) * inv_s;
                    g_kx[tid * XX + k] = expf(-0.5f * z * z);
                }
            }
            // lev -> kp (len 16)
            {
                float m = mean_lev[tid], inv_s = 1.0f / expf(logstd_lev[tid]);
                #pragma unroll
                for (int k = 0; k < PP; ++k) {
                    float c = -1.0f + 2.0f * (float)k / (float)(PP - 1);
                    float z = (c - m) * inv_s;
                    g_kp[tid * PP + k] = expf(-0.5f * z * z);
                }
            }
            // time -> kt (len 8)
            {
                float inv_tau = 1.0f / (expf(logtau[tid]) + 1e-4f);
                #pragma unroll
                for (int t = 0; t < TT; ++t)
                    g_kt[tid * TT + t] = expf(-(float)t * inv_tau);
            }
            g_integral[tid] = 0.0f;
        }
        #pragma unroll
        for (int j = tid; j < NF*NK*BB; j += 256)
            out[j] = 0.0f;
    }
}

// ---- Kernel 2: main fused pass + integral side-job ----
// grid = 1024 = (b:32) x (ychunk:16, 2 y each) x (fhalf:2)
// 256 threads = 8 warps = (f_local:4) x (k-half:2). Lane owns (p, t-quad).
// Also: block bx computes integral partial for cell (y,x) = (bx>>5, bx&31).
__global__ __launch_bounds__(256, 2)
void feat_kernel(const float* __restrict__ field, const float* __restrict__ quad,
                 float* __restrict__ out) {
    __shared__ float4 sq4[1024];             // 16KB quad row
    __shared__ float2 s_cf[4 * 8 * 32];      // 8KB: ky*kx per (f_local, k-pair, x)
    __shared__ float  s_iq[128];             // integral side-job qmean cell

    const int tid  = threadIdx.x;
    const int lane = tid & 31;
    const int wid  = tid >> 5;
    const int f_local = wid >> 1;
    const int kh   = wid & 1;
    const int bx   = blockIdx.x;
    const int b    = bx >> 5;
    const int ych  = (bx >> 1) & 15;
    const int fh   = bx & 1;
    const int f    = fh * 4 + f_local;
    const int p    = lane >> 1;
    const int t0   = (lane & 1) * 4;

    // integral side-job, part 1: stage this block's (y,x) cell of qmean
    if (tid < 128) s_iq[tid] = g_qmean[bx * (PP*TT) + tid];

    // per-lane packed weights for this warp's 4 k-pairs
    float2 w2[4][4];
    #pragma unroll
    for (int m = 0; m < 4; ++m) {
        int k0 = 2 * (kh * 4 + m);
        float kp0 = g_kp[(f * NK + k0) * PP + p];
        float kp1 = g_kp[(f * NK + k0 + 1) * PP + p];
        #pragma unroll
        for (int j = 0; j < 4; ++j) {
            w2[m][j].x = kp0 * g_kt[(f * NK + k0) * TT + t0 + j];
            w2[m][j].y = kp1 * g_kt[(f * NK + k0 + 1) * TT + t0 + j];
        }
    }
    __syncthreads();

    // integral side-job, part 2: separable contraction for cell (y,x)=(bx>>5, bx&31)
    if (tid < 128) {
        const float* kt = &g_kt[tid * TT];
        const float* kp = &g_kp[tid * PP];
        float s = 0.0f;
        #pragma unroll
        for (int pp = 0; pp < PP; ++pp) {
            float st = 0.0f;
            #pragma unroll
            for (int t = 0; t < TT; ++t)
                st += kt[t] * s_iq[pp * TT + t];
            s += kp[pp] * st;
        }
        int yc = bx >> 5, xc = bx & 31;
        atomicAdd(&g_integral[tid], s * g_ky[tid * YY + yc] * g_kx[tid * XX + xc]);
    }

    float2 acc[4];
    #pragma unroll
    for (int m = 0; m < 4; ++m) acc[m] = make_float2(0.0f, 0.0f);

    for (int yy = 0; yy < 2; ++yy) {
        int y = ych * 2 + yy;
        __syncthreads();
        // stage quad row (16KB), coalesced
        const float4* qrow = reinterpret_cast<const float4*>(quad + (size_t)(b * YY + y) * 4096);
        #pragma unroll
        for (int i = 0; i < 4; ++i)
            sq4[tid + 256 * i] = qrow[tid + 256 * i];
        // build ky*kx table: 1024 float2, 4 per thread
        #pragma unroll
        for (int e = 0; e < 4; ++e) {
            int idx = tid * 4 + e;
            int fl = idx >> 8;
            int kp_i = (idx >> 5) & 7;
            int x = idx & 31;
            int fg = fh * 4 + fl;
            int k0 = 2 * kp_i;
            s_cf[idx] = make_float2(
                g_ky[(fg * NK + k0) * YY + y] * g_kx[(fg * NK + k0) * XX + x],
                g_ky[(fg * NK + k0 + 1) * YY + y] * g_kx[(fg * NK + k0 + 1) * XX + x]);
        }
        __syncthreads();

        const float4* frow = reinterpret_cast<const float4*>(
            field + (size_t)((b * NF + f) * YY + y) * 4096);
        const float2* cf = &s_cf[(f_local * 8 + kh * 4) * 32];

        #pragma unroll 8
        for (int x = 0; x < XX; ++x) {
            float4 fv = frow[x * 32 + lane];   // contiguous 512B per warp-instr
            float4 qv = sq4[x * 32 + lane];    // conflict-free LDS.128
            float g0 = fv.x * qv.x;
            float g1 = fv.y * qv.y;
            float g2 = fv.z * qv.z;
            float g3 = fv.w * qv.w;
            float2 gg0 = make_float2(g0, g0);
            float2 gg1 = make_float2(g1, g1);
            float2 gg2 = make_float2(g2, g2);
            float2 gg3 = make_float2(g3, g3);
            #pragma unroll
            for (int m = 0; m < 4; ++m) {
                float2 s = fmul2(gg0, w2[m][0]);
                s = ffma2(gg1, w2[m][1], s);
                s = ffma2(gg2, w2[m][2], s);
                s = ffma2(gg3, w2[m][3], s);
                acc[m] = ffma2(s, cf[m * 32 + x], acc[m]);
            }
        }
    }

    // warp reduction over lanes (= over p,t), one atomic per k
    #pragma unroll
    for (int m = 0; m < 4; ++m) {
        float sx = acc[m].x, sy = acc[m].y;
        #pragma unroll
        for (int off = 16; off > 0; off >>= 1) {
            sx += __shfl_down_sync(0xffffffffu, sx, off);
            sy += __shfl_down_sync(0xffffffffu, sy, off);
        }
        if (lane == 0) {
            int kbase = b * (NF * NK) + f * NK + kh * 8 + 2 * m;
            atomicAdd(&out[kbase],     sx);
            atomicAdd(&out[kbase + 1], sy);
        }
    }
}

// ---- Kernel 3: normalize by integral ----
__global__ void norm_kernel(float* __restrict__ out) {
    int i = blockIdx.x * 256 + threadIdx.x;   // 4096
    out[i] = out[i] / (g_integral[i & 127] + 1e-4f);
}

extern "C" void kernel_launch(void* const* d_in, const int* in_sizes, int n_in,
                              void* d_out, int out_size) {
    const float* field      = (const float*)d_in[0];
    const float* quad       = (const float*)d_in[1];
    const float* mean_lat   = (const float*)d_in[2];
    const float* logstd_lat = (const float*)d_in[3];
    const float* mean_lon   = (const float*)d_in[4];
    const float* logstd_lon = (const float*)d_in[5];
    const float* mean_lev   = (const float*)d_in[6];
    const float* logstd_lev = (const float*)d_in[7];
    const float* logtau     = (const float*)d_in[8];
    float* out = (float*)d_out;

    prep_kernel<<<512, 256>>>(quad, mean_lat, logstd_lat, mean_lon, logstd_lon,
                              mean_lev, logstd_lev, logtau, out);
    feat_kernel<<<1024, 256>>>(field, quad, out);
    norm_kernel<<<16, 256>>>(out);
}